// round 1
// baseline (speedup 1.0000x reference)
#include <cuda_runtime.h>

// Wilson Dslash on a 32^4 lattice, 4 spins x 3 colors, complex split re/im.
// Hardcoded DeGrand-Rossi projector structure (I -/+ gamma_mu are rank-2):
//   forward term (Pm = I - g_mu), backward term (Pp = I + g_mu, with U^dagger at x-mu).
// Half-spinor projection -> 3x3 complex matvec on 2 spins -> reconstruction.

static constexpr int VOL = 1 << 20;  // 32^4

template<int MU, bool DAG>
__device__ __forceinline__ void dslash_term(
    const float* __restrict__ pr, const float* __restrict__ pi,   // psi at neighbor (12 floats each)
    const float* __restrict__ ur, const float* __restrict__ ui,   // U 3x3 complex (9 floats each)
    float* ar, float* ai)                                          // accumulators [12]
{
    float Ur[9], Ui[9];
#pragma unroll
    for (int k = 0; k < 9; k++) { Ur[k] = __ldg(ur + k); Ui[k] = __ldg(ui + k); }

    // Project neighbor spinor to half-spinor h[2 spins][3 colors]
    float hr[6], hi[6];
#pragma unroll
    for (int c = 0; c < 3; c++) {
        float p0r = __ldg(pr + c),     p0i = __ldg(pi + c);
        float p1r = __ldg(pr + 3 + c), p1i = __ldg(pi + 3 + c);
        float p2r = __ldg(pr + 6 + c), p2i = __ldg(pi + 6 + c);
        float p3r = __ldg(pr + 9 + c), p3i = __ldg(pi + 9 + c);
        float h0r, h0i, h1r, h1i;
        if (MU == 0) {
            if (!DAG) { h0r = p0r + p3i; h0i = p0i - p3r; h1r = p1r + p2i; h1i = p1i - p2r; }
            else      { h0r = p0r - p3i; h0i = p0i + p3r; h1r = p1r - p2i; h1i = p1i + p2r; }
        } else if (MU == 1) {
            if (!DAG) { h0r = p0r + p3r; h0i = p0i + p3i; h1r = p1r - p2r; h1i = p1i - p2i; }
            else      { h0r = p0r - p3r; h0i = p0i - p3i; h1r = p1r + p2r; h1i = p1i + p2i; }
        } else if (MU == 2) {
            if (!DAG) { h0r = p0r + p2i; h0i = p0i - p2r; h1r = p1r - p3i; h1i = p1i + p3r; }
            else      { h0r = p0r - p2i; h0i = p0i + p2r; h1r = p1r + p3i; h1i = p1i - p3r; }
        } else {
            if (!DAG) { h0r = p0r - p2r; h0i = p0i - p2i; h1r = p1r - p3r; h1i = p1i - p3i; }
            else      { h0r = p0r + p2r; h0i = p0i + p2i; h1r = p1r + p3r; h1i = p1i + p3i; }
        }
        hr[c] = h0r; hi[c] = h0i; hr[3 + c] = h1r; hi[3 + c] = h1i;
    }

    // Color matvec: g = U h (forward) or U^dagger h (backward)
    float gr[6], gi[6];
#pragma unroll
    for (int s = 0; s < 2; s++) {
#pragma unroll
        for (int i = 0; i < 3; i++) {
            float rr = 0.f, ii = 0.f;
#pragma unroll
            for (int j = 0; j < 3; j++) {
                float urv, uiv;
                if (!DAG) { urv = Ur[i * 3 + j]; uiv = Ui[i * 3 + j]; }
                else      { urv = Ur[j * 3 + i]; uiv = -Ui[j * 3 + i]; }
                rr += urv * hr[s * 3 + j] - uiv * hi[s * 3 + j];
                ii += urv * hi[s * 3 + j] + uiv * hr[s * 3 + j];
            }
            gr[s * 3 + i] = rr; gi[s * 3 + i] = ii;
        }
    }

    // Reconstruct 4 spins and accumulate
#pragma unroll
    for (int c = 0; c < 3; c++) {
        ar[c]     += gr[c];     ai[c]     += gi[c];
        ar[3 + c] += gr[3 + c]; ai[3 + c] += gi[3 + c];
        if (MU == 0) {
            if (!DAG) { // r2 = i*g1, r3 = i*g0
                ar[6 + c] -= gi[3 + c]; ai[6 + c] += gr[3 + c];
                ar[9 + c] -= gi[c];     ai[9 + c] += gr[c];
            } else {    // r2 = -i*g1, r3 = -i*g0
                ar[6 + c] += gi[3 + c]; ai[6 + c] -= gr[3 + c];
                ar[9 + c] += gi[c];     ai[9 + c] -= gr[c];
            }
        } else if (MU == 1) {
            if (!DAG) { // r2 = -g1, r3 = +g0
                ar[6 + c] -= gr[3 + c]; ai[6 + c] -= gi[3 + c];
                ar[9 + c] += gr[c];     ai[9 + c] += gi[c];
            } else {    // r2 = +g1, r3 = -g0
                ar[6 + c] += gr[3 + c]; ai[6 + c] += gi[3 + c];
                ar[9 + c] -= gr[c];     ai[9 + c] -= gi[c];
            }
        } else if (MU == 2) {
            if (!DAG) { // r2 = i*g0, r3 = -i*g1
                ar[6 + c] -= gi[c];     ai[6 + c] += gr[c];
                ar[9 + c] += gi[3 + c]; ai[9 + c] -= gr[3 + c];
            } else {    // r2 = -i*g0, r3 = i*g1
                ar[6 + c] += gi[c];     ai[6 + c] -= gr[c];
                ar[9 + c] -= gi[3 + c]; ai[9 + c] += gr[3 + c];
            }
        } else {
            if (!DAG) { // r2 = -g0, r3 = -g1
                ar[6 + c] -= gr[c];     ai[6 + c] -= gi[c];
                ar[9 + c] -= gr[3 + c]; ai[9 + c] -= gi[3 + c];
            } else {    // r2 = +g0, r3 = +g1
                ar[6 + c] += gr[c];     ai[6 + c] += gi[c];
                ar[9 + c] += gr[3 + c]; ai[9 + c] += gi[3 + c];
            }
        }
    }
}

__global__ void wilson_dslash_kernel(
    const float* __restrict__ psi_re, const float* __restrict__ psi_im,
    const float* __restrict__ U_re,   const float* __restrict__ U_im,
    float* __restrict__ out_re, float* __restrict__ out_im)
{
    int site = blockIdx.x * blockDim.x + threadIdx.x;
    int x3 = site & 31, x2 = (site >> 5) & 31, x1 = (site >> 10) & 31, x0 = (site >> 15) & 31;

    float ar[12], ai[12];
#pragma unroll
    for (int k = 0; k < 12; k++) { ar[k] = 0.f; ai[k] = 0.f; }

    int fw0 = (x0 == 31) ? site - (31 << 15) : site + (1 << 15);
    int bw0 = (x0 == 0)  ? site + (31 << 15) : site - (1 << 15);
    int fw1 = (x1 == 31) ? site - (31 << 10) : site + (1 << 10);
    int bw1 = (x1 == 0)  ? site + (31 << 10) : site - (1 << 10);
    int fw2 = (x2 == 31) ? site - (31 << 5)  : site + (1 << 5);
    int bw2 = (x2 == 0)  ? site + (31 << 5)  : site - (1 << 5);
    int fw3 = (x3 == 31) ? site - 31 : site + 1;
    int bw3 = (x3 == 0)  ? site + 31 : site - 1;

    const size_t s36 = (size_t)site * 36;

    dslash_term<0, false>(psi_re + (size_t)fw0 * 12, psi_im + (size_t)fw0 * 12,
                          U_re + s36 + 0,  U_im + s36 + 0,  ar, ai);
    dslash_term<0, true >(psi_re + (size_t)bw0 * 12, psi_im + (size_t)bw0 * 12,
                          U_re + (size_t)bw0 * 36 + 0,  U_im + (size_t)bw0 * 36 + 0,  ar, ai);

    dslash_term<1, false>(psi_re + (size_t)fw1 * 12, psi_im + (size_t)fw1 * 12,
                          U_re + s36 + 9,  U_im + s36 + 9,  ar, ai);
    dslash_term<1, true >(psi_re + (size_t)bw1 * 12, psi_im + (size_t)bw1 * 12,
                          U_re + (size_t)bw1 * 36 + 9,  U_im + (size_t)bw1 * 36 + 9,  ar, ai);

    dslash_term<2, false>(psi_re + (size_t)fw2 * 12, psi_im + (size_t)fw2 * 12,
                          U_re + s36 + 18, U_im + s36 + 18, ar, ai);
    dslash_term<2, true >(psi_re + (size_t)bw2 * 12, psi_im + (size_t)bw2 * 12,
                          U_re + (size_t)bw2 * 36 + 18, U_im + (size_t)bw2 * 36 + 18, ar, ai);

    dslash_term<3, false>(psi_re + (size_t)fw3 * 12, psi_im + (size_t)fw3 * 12,
                          U_re + s36 + 27, U_im + s36 + 27, ar, ai);
    dslash_term<3, true >(psi_re + (size_t)bw3 * 12, psi_im + (size_t)bw3 * 12,
                          U_re + (size_t)bw3 * 36 + 27, U_im + (size_t)bw3 * 36 + 27, ar, ai);

    size_t o = (size_t)site * 12;
#pragma unroll
    for (int k = 0; k < 12; k++) {
        out_re[o + k] = -0.5f * ar[k];
        out_im[o + k] = -0.5f * ai[k];
    }
}

extern "C" void kernel_launch(void* const* d_in, const int* in_sizes, int n_in,
                              void* d_out, int out_size) {
    const float* psi_re = (const float*)d_in[0];
    const float* psi_im = (const float*)d_in[1];
    const float* U_re   = (const float*)d_in[2];
    const float* U_im   = (const float*)d_in[3];
    // d_in[4..7] are the projector matrices; their structure is hardcoded above.
    float* out = (float*)d_out;
    float* out_re = out;
    float* out_im = out + (size_t)VOL * 12;

    wilson_dslash_kernel<<<VOL / 256, 256>>>(psi_re, psi_im, U_re, U_im, out_re, out_im);
}

// round 3
// speedup vs baseline: 2.0677x; 2.0677x over previous
#include <cuda_runtime.h>

// Wilson Dslash, 32^4 lattice, DeGrand-Rossi basis, half-spinor trick.
// R3 (= R2 resubmit after infra failure): fully vectorized loads/stores
// (LDG.128/LDG.64 with compile-time alignment-aware U loader) to relieve
// the L1tex bottleneck seen in R1.

static constexpr int VOL = 1 << 20;  // 32^4

// Load 9 consecutive floats from a pointer whose byte address is A mod 16
// (A in {0,4,8,12}, compile-time).
template<int A>
__device__ __forceinline__ void load9(const float* __restrict__ p, float* v) {
    if (A == 0) {
        float4 a = __ldg((const float4*)p);
        float4 b = __ldg((const float4*)(p + 4));
        v[0]=a.x; v[1]=a.y; v[2]=a.z; v[3]=a.w;
        v[4]=b.x; v[5]=b.y; v[6]=b.z; v[7]=b.w;
        v[8]=__ldg(p + 8);
    } else if (A == 4) {
        v[0]=__ldg(p);
        float2 c = __ldg((const float2*)(p + 1));
        float4 d = __ldg((const float4*)(p + 3));
        float2 e = __ldg((const float2*)(p + 7));
        v[1]=c.x; v[2]=c.y; v[3]=d.x; v[4]=d.y; v[5]=d.z; v[6]=d.w;
        v[7]=e.x; v[8]=e.y;
    } else if (A == 8) {
        float2 a = __ldg((const float2*)p);
        float4 b = __ldg((const float4*)(p + 2));
        float2 c = __ldg((const float2*)(p + 6));
        v[0]=a.x; v[1]=a.y; v[2]=b.x; v[3]=b.y; v[4]=b.z; v[5]=b.w;
        v[6]=c.x; v[7]=c.y; v[8]=__ldg(p + 8);
    } else {  // A == 12
        v[0]=__ldg(p);
        float4 b = __ldg((const float4*)(p + 1));
        float4 c = __ldg((const float4*)(p + 5));
        v[1]=b.x; v[2]=b.y; v[3]=b.z; v[4]=b.w;
        v[5]=c.x; v[6]=c.y; v[7]=c.z; v[8]=c.w;
    }
}

// Load 12 consecutive floats (16B-aligned base).
__device__ __forceinline__ void load12(const float* __restrict__ p, float* v) {
    float4 a = __ldg((const float4*)p);
    float4 b = __ldg((const float4*)(p + 4));
    float4 c = __ldg((const float4*)(p + 8));
    v[0]=a.x; v[1]=a.y; v[2]=a.z;  v[3]=a.w;
    v[4]=b.x; v[5]=b.y; v[6]=b.z;  v[7]=b.w;
    v[8]=c.x; v[9]=c.y; v[10]=c.z; v[11]=c.w;
}

template<int MU, bool DAG>
__device__ __forceinline__ void dslash_term(
    const float* __restrict__ pr, const float* __restrict__ pi,   // psi at neighbor
    const float* __restrict__ ur, const float* __restrict__ ui,   // U 3x3 complex
    float* ar, float* ai)                                          // accumulators [12]
{
    constexpr int A = (MU * 36) & 15;  // byte alignment of U matrix base mod 16
    float Ur[9], Ui[9];
    load9<A>(ur, Ur);
    load9<A>(ui, Ui);

    float Pr[12], Pi[12];
    load12(pr, Pr);
    load12(pi, Pi);

    // Project to half-spinor h[2][3]
    float hr[6], hi[6];
#pragma unroll
    for (int c = 0; c < 3; c++) {
        float p0r = Pr[c],     p0i = Pi[c];
        float p1r = Pr[3 + c], p1i = Pi[3 + c];
        float p2r = Pr[6 + c], p2i = Pi[6 + c];
        float p3r = Pr[9 + c], p3i = Pi[9 + c];
        float h0r, h0i, h1r, h1i;
        if (MU == 0) {
            if (!DAG) { h0r = p0r + p3i; h0i = p0i - p3r; h1r = p1r + p2i; h1i = p1i - p2r; }
            else      { h0r = p0r - p3i; h0i = p0i + p3r; h1r = p1r - p2i; h1i = p1i + p2r; }
        } else if (MU == 1) {
            if (!DAG) { h0r = p0r + p3r; h0i = p0i + p3i; h1r = p1r - p2r; h1i = p1i - p2i; }
            else      { h0r = p0r - p3r; h0i = p0i - p3i; h1r = p1r + p2r; h1i = p1i + p2i; }
        } else if (MU == 2) {
            if (!DAG) { h0r = p0r + p2i; h0i = p0i - p2r; h1r = p1r - p3i; h1i = p1i + p3r; }
            else      { h0r = p0r - p2i; h0i = p0i + p2r; h1r = p1r + p3i; h1i = p1i - p3r; }
        } else {
            if (!DAG) { h0r = p0r - p2r; h0i = p0i - p2i; h1r = p1r - p3r; h1i = p1i - p3i; }
            else      { h0r = p0r + p2r; h0i = p0i + p2i; h1r = p1r + p3r; h1i = p1i + p3i; }
        }
        hr[c] = h0r; hi[c] = h0i; hr[3 + c] = h1r; hi[3 + c] = h1i;
    }

    // Color matvec: g = U h (forward) or U^dag h (backward)
    float gr[6], gi[6];
#pragma unroll
    for (int s = 0; s < 2; s++) {
#pragma unroll
        for (int i = 0; i < 3; i++) {
            float rr = 0.f, ii = 0.f;
#pragma unroll
            for (int j = 0; j < 3; j++) {
                float urv, uiv;
                if (!DAG) { urv = Ur[i * 3 + j]; uiv = Ui[i * 3 + j]; }
                else      { urv = Ur[j * 3 + i]; uiv = -Ui[j * 3 + i]; }
                rr += urv * hr[s * 3 + j] - uiv * hi[s * 3 + j];
                ii += urv * hi[s * 3 + j] + uiv * hr[s * 3 + j];
            }
            gr[s * 3 + i] = rr; gi[s * 3 + i] = ii;
        }
    }

    // Reconstruct 4 spins and accumulate
#pragma unroll
    for (int c = 0; c < 3; c++) {
        ar[c]     += gr[c];     ai[c]     += gi[c];
        ar[3 + c] += gr[3 + c]; ai[3 + c] += gi[3 + c];
        if (MU == 0) {
            if (!DAG) {
                ar[6 + c] -= gi[3 + c]; ai[6 + c] += gr[3 + c];
                ar[9 + c] -= gi[c];     ai[9 + c] += gr[c];
            } else {
                ar[6 + c] += gi[3 + c]; ai[6 + c] -= gr[3 + c];
                ar[9 + c] += gi[c];     ai[9 + c] -= gr[c];
            }
        } else if (MU == 1) {
            if (!DAG) {
                ar[6 + c] -= gr[3 + c]; ai[6 + c] -= gi[3 + c];
                ar[9 + c] += gr[c];     ai[9 + c] += gi[c];
            } else {
                ar[6 + c] += gr[3 + c]; ai[6 + c] += gi[3 + c];
                ar[9 + c] -= gr[c];     ai[9 + c] -= gi[c];
            }
        } else if (MU == 2) {
            if (!DAG) {
                ar[6 + c] -= gi[c];     ai[6 + c] += gr[c];
                ar[9 + c] += gi[3 + c]; ai[9 + c] -= gr[3 + c];
            } else {
                ar[6 + c] += gi[c];     ai[6 + c] -= gr[c];
                ar[9 + c] -= gi[3 + c]; ai[9 + c] += gr[3 + c];
            }
        } else {
            if (!DAG) {
                ar[6 + c] -= gr[c];     ai[6 + c] -= gi[c];
                ar[9 + c] -= gr[3 + c]; ai[9 + c] -= gi[3 + c];
            } else {
                ar[6 + c] += gr[c];     ai[6 + c] += gi[c];
                ar[9 + c] += gr[3 + c]; ai[9 + c] += gi[3 + c];
            }
        }
    }
}

__global__ void __launch_bounds__(128) wilson_dslash_kernel(
    const float* __restrict__ psi_re, const float* __restrict__ psi_im,
    const float* __restrict__ U_re,   const float* __restrict__ U_im,
    float* __restrict__ out_re, float* __restrict__ out_im)
{
    int site = blockIdx.x * blockDim.x + threadIdx.x;
    int x3 = site & 31, x2 = (site >> 5) & 31, x1 = (site >> 10) & 31, x0 = (site >> 15) & 31;

    float ar[12], ai[12];
#pragma unroll
    for (int k = 0; k < 12; k++) { ar[k] = 0.f; ai[k] = 0.f; }

    int fw0 = (x0 == 31) ? site - (31 << 15) : site + (1 << 15);
    int bw0 = (x0 == 0)  ? site + (31 << 15) : site - (1 << 15);
    int fw1 = (x1 == 31) ? site - (31 << 10) : site + (1 << 10);
    int bw1 = (x1 == 0)  ? site + (31 << 10) : site - (1 << 10);
    int fw2 = (x2 == 31) ? site - (31 << 5)  : site + (1 << 5);
    int bw2 = (x2 == 0)  ? site + (31 << 5)  : site - (1 << 5);
    int fw3 = (x3 == 31) ? site - 31 : site + 1;
    int bw3 = (x3 == 0)  ? site + 31 : site - 1;

    const size_t s36 = (size_t)site * 36;

    dslash_term<0, false>(psi_re + (size_t)fw0 * 12, psi_im + (size_t)fw0 * 12,
                          U_re + s36 + 0,  U_im + s36 + 0,  ar, ai);
    dslash_term<0, true >(psi_re + (size_t)bw0 * 12, psi_im + (size_t)bw0 * 12,
                          U_re + (size_t)bw0 * 36 + 0,  U_im + (size_t)bw0 * 36 + 0,  ar, ai);

    dslash_term<1, false>(psi_re + (size_t)fw1 * 12, psi_im + (size_t)fw1 * 12,
                          U_re + s36 + 9,  U_im + s36 + 9,  ar, ai);
    dslash_term<1, true >(psi_re + (size_t)bw1 * 12, psi_im + (size_t)bw1 * 12,
                          U_re + (size_t)bw1 * 36 + 9,  U_im + (size_t)bw1 * 36 + 9,  ar, ai);

    dslash_term<2, false>(psi_re + (size_t)fw2 * 12, psi_im + (size_t)fw2 * 12,
                          U_re + s36 + 18, U_im + s36 + 18, ar, ai);
    dslash_term<2, true >(psi_re + (size_t)bw2 * 12, psi_im + (size_t)bw2 * 12,
                          U_re + (size_t)bw2 * 36 + 18, U_im + (size_t)bw2 * 36 + 18, ar, ai);

    dslash_term<3, false>(psi_re + (size_t)fw3 * 12, psi_im + (size_t)fw3 * 12,
                          U_re + s36 + 27, U_im + s36 + 27, ar, ai);
    dslash_term<3, true >(psi_re + (size_t)bw3 * 12, psi_im + (size_t)bw3 * 12,
                          U_re + (size_t)bw3 * 36 + 27, U_im + (size_t)bw3 * 36 + 27, ar, ai);

    size_t o = (size_t)site * 12;
    float4 v;
    v.x = -0.5f * ar[0]; v.y = -0.5f * ar[1]; v.z = -0.5f * ar[2];  v.w = -0.5f * ar[3];
    *(float4*)(out_re + o)     = v;
    v.x = -0.5f * ar[4]; v.y = -0.5f * ar[5]; v.z = -0.5f * ar[6];  v.w = -0.5f * ar[7];
    *(float4*)(out_re + o + 4) = v;
    v.x = -0.5f * ar[8]; v.y = -0.5f * ar[9]; v.z = -0.5f * ar[10]; v.w = -0.5f * ar[11];
    *(float4*)(out_re + o + 8) = v;
    v.x = -0.5f * ai[0]; v.y = -0.5f * ai[1]; v.z = -0.5f * ai[2];  v.w = -0.5f * ai[3];
    *(float4*)(out_im + o)     = v;
    v.x = -0.5f * ai[4]; v.y = -0.5f * ai[5]; v.z = -0.5f * ai[6];  v.w = -0.5f * ai[7];
    *(float4*)(out_im + o + 4) = v;
    v.x = -0.5f * ai[8]; v.y = -0.5f * ai[9]; v.z = -0.5f * ai[10]; v.w = -0.5f * ai[11];
    *(float4*)(out_im + o + 8) = v;
}

extern "C" void kernel_launch(void* const* d_in, const int* in_sizes, int n_in,
                              void* d_out, int out_size) {
    const float* psi_re = (const float*)d_in[0];
    const float* psi_im = (const float*)d_in[1];
    const float* U_re   = (const float*)d_in[2];
    const float* U_im   = (const float*)d_in[3];
    float* out = (float*)d_out;
    float* out_re = out;
    float* out_im = out + (size_t)VOL * 12;

    wilson_dslash_kernel<<<VOL / 128, 128>>>(psi_re, psi_im, U_re, U_im, out_re, out_im);
}